// round 16
// baseline (speedup 1.0000x reference)
#include <cuda_runtime.h>
#include <cuda_fp16.h>
#include <cstdint>

// ---------------------------------------------------------------------------
// TFN forward. R16: R15 with tail_a reshaped. Old tail_a (512 blk x 96 thr,
// 19 strided loads/thread) measured 12.8us at 293GB/s, occ 15% - pure
// latency exposure. New tail_a: grid (24,8) x 256 thr; thread owns one flat
// (b,h) element (coalesced across tid), sums 19 partials stride-8 (MLP 19).
// Everything else byte-identical to R15 (best, 95.0us).
// ---------------------------------------------------------------------------

#define NBLK   152
#define BDIM   64
#define HDIM   96
#define LDH2   56             // smem B row stride in halfs (112 B)
#define KR2    112            // 97 data rows + 15 zero rows (7 k16 steps)
#define WBUFH2 (KR2 * LDH2)   // 6272 halfs = 12544 B per stage
#define SMEM_BYTES (3*WBUFH2*2 + 6208*4 + 128*4)

__device__ float g_a1[BDIM * 97];
__device__ float g_v1[BDIM * 97];
__device__ float g_t1[BDIM * 97];
__device__ float g_part[NBLK * BDIM * HDIM];
__device__ float g_epart[16 * BDIM * HDIM];   // enc k-slice partials
__device__ float g_ypart[8 * BDIM * HDIM];    // tail first-level partials

// ---------------------------------------------------------------------------

__device__ __forceinline__ uint32_t h2u(__half2 h) {
    return *reinterpret_cast<uint32_t*>(&h);
}

__device__ __forceinline__ void mma_f16(float c[4],
                                        uint32_t a0, uint32_t a1,
                                        uint32_t a2, uint32_t a3,
                                        uint32_t b0, uint32_t b1) {
    asm volatile(
        "mma.sync.aligned.m16n8k16.row.col.f32.f16.f16.f32 "
        "{%0,%1,%2,%3}, {%4,%5,%6,%7}, {%8,%9}, {%0,%1,%2,%3};"
        : "+f"(c[0]), "+f"(c[1]), "+f"(c[2]), "+f"(c[3])
        : "r"(a0), "r"(a1), "r"(a2), "r"(a3), "r"(b0), "r"(b1));
}

struct __align__(8) H4 { __half2 a, b; };

// CTA loads its N-half of a chunk: 97 rows x 48 cols = 1164 float4.
__device__ __forceinline__ void stage_ldg(float4 (&stg)[5],
                                          const float* __restrict__ W1,
                                          int av, int nh, int tid) {
    const float* src = W1 + (size_t)av * 9312 + nh * 48;
#pragma unroll
    for (int j = 0; j < 4; j++) {
        int q = tid + j * 256;
        int t = q / 12, c = (q - 12 * t) * 4;
        stg[j] = *reinterpret_cast<const float4*>(src + t * 96 + c);
    }
    if (tid < 140) {
        int q = tid + 1024;
        int t = q / 12, c = (q - 12 * t) * 4;
        stg[4] = *reinterpret_cast<const float4*>(src + t * 96 + c);
    }
}

__device__ __forceinline__ void cvt_store(__half* buf, int q, float4 v) {
    int t = q / 12;
    int c = (q - 12 * t) * 4;
    H4 o;
    o.a = __floats2half2_rn(v.x, v.y);
    o.b = __floats2half2_rn(v.z, v.w);
    *reinterpret_cast<H4*>(buf + t * LDH2 + c) = o;
}

__device__ __forceinline__ void stage_sts(__half* buf, const float4 (&stg)[5],
                                          int tid) {
#pragma unroll
    for (int j = 0; j < 4; j++) cvt_store(buf, tid + j * 256, stg[j]);
    if (tid < 140) cvt_store(buf, tid + 1024, stg[4]);
}

// ---------------------------------------------------------------------------
// Kernel 1a: enc partial GEMM. grid (64 b, 16 modslice), 192 thr = 96h x 2g.
// ---------------------------------------------------------------------------
__global__ void __launch_bounds__(192) tfn_enc_gemm(
    const float* __restrict__ audios, const float* __restrict__ texts,
    const float* __restrict__ videos,
    const float* __restrict__ Wa, const float* __restrict__ Wt,
    const float* __restrict__ Wv) {
    const int b   = blockIdx.x;
    const int ms  = blockIdx.y;
    const int tid = threadIdx.x;

    const float* x; const float* W; int K, k0;
    if (ms < 4)       { x = audios; W = Wa; K = 512;  k0 = ms * 128; }
    else if (ms < 12) { x = texts;  W = Wt; K = 1024; k0 = (ms - 4) * 128; }
    else              { x = videos; W = Wv; K = 512;  k0 = (ms - 12) * 128; }

    __shared__ float xs[128];
    __shared__ float ps[192];

    if (tid < 128) xs[tid] = x[(size_t)b * K + k0 + tid];
    __syncthreads();

    const int h = tid % 96;
    const int g = tid / 96;   // 0..1, 64 k each
    const float* Wp = W + (size_t)(k0 + g * 64) * HDIM + h;
    const float* xp = xs + g * 64;

    float acc = 0.f;
#pragma unroll 8
    for (int k = 0; k < 64; k++)
        acc += xp[k] * Wp[k * HDIM];
    ps[tid] = acc;
    __syncthreads();

    if (g == 0)
        g_epart[(ms * 64 + b) * HDIM + h] = ps[h] + ps[h + 96];
}

// ---------------------------------------------------------------------------
// Kernel 1b: enc reduce + bias + relu + ones column. grid (64, 3), 96 thr.
// ---------------------------------------------------------------------------
__global__ void __launch_bounds__(96) tfn_enc_reduce(
    const float* __restrict__ ba, const float* __restrict__ bt,
    const float* __restrict__ bv) {
    const int b   = blockIdx.x;
    const int mod = blockIdx.y;
    const int h   = threadIdx.x;

    const float* bias; float* out; int s0, s1;
    if (mod == 0)      { bias = ba; out = g_a1; s0 = 0;  s1 = 4; }
    else if (mod == 1) { bias = bt; out = g_t1; s0 = 4;  s1 = 12; }
    else               { bias = bv; out = g_v1; s0 = 12; s1 = 16; }

    float acc = bias[h];
#pragma unroll
    for (int s = s0; s < s1; s++)
        acc += g_epart[(s * 64 + b) * HDIM + h];
    out[b * 97 + 1 + h] = fmaxf(acc, 0.f);
    if (h == 0) out[b * 97] = 1.f;
}

// ---------------------------------------------------------------------------
// Kernel 2: main fused trilinear GEMM (R14 verbatim). grid 304, 256 thr,
// 2 CTAs/SM, prefetch distance 3.
// ---------------------------------------------------------------------------
__global__ void __launch_bounds__(256, 2) tfn_main(const float* __restrict__ W1) {
    extern __shared__ char smx[];
    __half* wb0 = reinterpret_cast<__half*>(smx);
    __half* wb1 = wb0 + WBUFH2;
    __half* wb2 = wb1 + WBUFH2;
    float*  v1s = reinterpret_cast<float*>(wb2 + WBUFH2);  // [64*97]
    float*  a1c = v1s + 6208;                              // [2*64]

    const int tid  = threadIdx.x;
    const int lane = tid & 31;
    const int wid  = tid >> 5;
    const int wm   = wid & 3;
    const int wn   = wid >> 2;
    const int gid  = lane >> 2;
    const int tig  = lane & 3;
    const int b0   = wm * 16 + gid;
    const int nbase = wn * 24;

    const int bk    = blockIdx.x;
    const int range = bk >> 1;
    const int nh    = bk & 1;
    const int cstart = (range < 137) ? range * 62 : range * 61 + 137;
    const int ccnt   = (range < 137) ? 62 : 61;
    const int caBase = cstart / 97;

    for (int i = tid; i < 6208; i += 256) v1s[i] = g_v1[i];
    if (tid < 128) {
        int b = tid & 63, col = tid >> 6;
        int ca = caBase + col; if (ca > 96) ca = 96;
        a1c[col * 64 + b] = g_a1[b * 97 + ca];
    }
    for (int i = tid; i < 3 * 420; i += 256) {
        int s = i / 420, r = i - s * 420;
        reinterpret_cast<uint32_t*>(wb0 + s * WBUFH2 + 97 * LDH2)[r] = 0;
    }

    __half2 t1f[7][4];
#pragma unroll
    for (int ks = 0; ks < 7; ks++) {
        int ka = ks * 16 + 2 * tig;
        int kb = ka + 8;
        float x0 = (ka     < 97) ? g_t1[b0 * 97 + ka]           : 0.f;
        float x1 = (ka + 1 < 97) ? g_t1[b0 * 97 + ka + 1]       : 0.f;
        float y0 = (ka     < 97) ? g_t1[(b0 + 8) * 97 + ka]     : 0.f;
        float y1 = (ka + 1 < 97) ? g_t1[(b0 + 8) * 97 + ka + 1] : 0.f;
        float x2 = (kb     < 97) ? g_t1[b0 * 97 + kb]           : 0.f;
        float x3 = (kb + 1 < 97) ? g_t1[b0 * 97 + kb + 1]       : 0.f;
        float y2 = (kb     < 97) ? g_t1[(b0 + 8) * 97 + kb]     : 0.f;
        float y3 = (kb + 1 < 97) ? g_t1[(b0 + 8) * 97 + kb + 1] : 0.f;
        t1f[ks][0] = __floats2half2_rn(x0, x1);
        t1f[ks][1] = __floats2half2_rn(y0, y1);
        t1f[ks][2] = __floats2half2_rn(x2, x3);
        t1f[ks][3] = __floats2half2_rn(y2, y3);
    }

    float Y[3][4];
#pragma unroll
    for (int j = 0; j < 3; j++) { Y[j][0] = Y[j][1] = Y[j][2] = Y[j][3] = 0.f; }

    const int lrow = lane & 15;
    const int lcol = (lane >> 4) * 8;

    auto compute = [&](int av, const __half* curb) {
        const int ca  = av / 97;
        const int cv  = av - ca * 97;
        const int cai = ca - caBase;
        const __half2 m0h = __float2half2_rn(a1c[cai * 64 + b0] * v1s[b0 * 97 + cv]);
        const __half2 m1h = __float2half2_rn(a1c[cai * 64 + b0 + 8] * v1s[(b0 + 8) * 97 + cv]);
#pragma unroll
        for (int ks = 0; ks < 7; ks++) {
            const uint32_t A0 = h2u(__hmul2(m0h, t1f[ks][0]));
            const uint32_t A1 = h2u(__hmul2(m1h, t1f[ks][1]));
            const uint32_t A2 = h2u(__hmul2(m0h, t1f[ks][2]));
            const uint32_t A3 = h2u(__hmul2(m1h, t1f[ks][3]));
            const __half* rowp = curb + (ks * 16 + lrow) * LDH2 + nbase;

            uint32_t s4 = (uint32_t)__cvta_generic_to_shared(rowp + lcol);
            uint32_t B0, B1, B2, B3;
            asm volatile(
                "ldmatrix.sync.aligned.m8n8.x4.trans.shared.b16 "
                "{%0,%1,%2,%3}, [%4];"
                : "=r"(B0), "=r"(B1), "=r"(B2), "=r"(B3) : "r"(s4));

            uint32_t s2 = (uint32_t)__cvta_generic_to_shared(rowp + 16);
            uint32_t C0, C1;
            asm volatile(
                "ldmatrix.sync.aligned.m8n8.x2.trans.shared.b16 "
                "{%0,%1}, [%2];"
                : "=r"(C0), "=r"(C1) : "r"(s2));

            mma_f16(Y[0], A0, A1, A2, A3, B0, B1);
            mma_f16(Y[1], A0, A1, A2, A3, B2, B3);
            mma_f16(Y[2], A0, A1, A2, A3, C0, C1);
        }
    };

    float4 stgA[5], stgB[5];
    stage_ldg(stgA, W1, cstart, nh, tid);
    if (ccnt > 1) stage_ldg(stgB, W1, cstart + 1, nh, tid);
    stage_sts(wb0, stgA, tid);
    if (ccnt > 2) stage_ldg(stgA, W1, cstart + 2, nh, tid);
    __syncthreads();

    __half *cur = wb0, *nxt = wb1, *spare = wb2;

    for (int ci = 0; ci < ccnt; ci += 2) {
        if (ci + 1 < ccnt) stage_sts(nxt, stgB, tid);
        if (ci + 3 < ccnt) stage_ldg(stgB, W1, cstart + ci + 3, nh, tid);
        compute(cstart + ci, cur);
        __syncthreads();
        { __half* t = cur; cur = nxt; nxt = spare; spare = t; }

        if (ci + 1 < ccnt) {
            if (ci + 2 < ccnt) stage_sts(nxt, stgA, tid);
            if (ci + 4 < ccnt) stage_ldg(stgA, W1, cstart + ci + 4, nh, tid);
            compute(cstart + ci + 1, cur);
            __syncthreads();
            { __half* t = cur; cur = nxt; nxt = spare; spare = t; }
        }
    }

    float* dst = g_part + (size_t)range * (BDIM * HDIM);
#pragma unroll
    for (int j = 0; j < 3; j++) {
        int h = nh * 48 + nbase + 8 * j + 2 * tig;
        *reinterpret_cast<float2*>(dst + b0 * HDIM + h) =
            make_float2(Y[j][0], Y[j][1]);
        *reinterpret_cast<float2*>(dst + (b0 + 8) * HDIM + h) =
            make_float2(Y[j][2], Y[j][3]);
    }
}

// ---------------------------------------------------------------------------
// Kernel 3a: first-level partial reduce, coalesced. grid (24, 8), 256 thr.
// Thread owns flat element e = bx*256+tid (consecutive -> coalesced lines);
// sums partials p = pg, pg+8, ... (19 independent loads, MLP-unrolled).
// ---------------------------------------------------------------------------
__global__ void __launch_bounds__(256) tfn_tail_a() {
    const int e  = blockIdx.x * 256 + threadIdx.x;   // 0..6143
    const int pg = blockIdx.y;                       // 0..7

    float acc = 0.f;
#pragma unroll
    for (int p = pg; p < NBLK; p += 8)
        acc += g_part[(size_t)p * (BDIM * HDIM) + e];
    g_ypart[pg * (BDIM * HDIM) + e] = acc;
}

// ---------------------------------------------------------------------------
// Kernel 3b: finish y1 + W2 + heads. grid 64, 384 thr = 96h x 4g.
// ---------------------------------------------------------------------------
__global__ void __launch_bounds__(384) tfn_tail_b(
    const float* __restrict__ b1, const float* __restrict__ W2,
    const float* __restrict__ b2,
    const float* __restrict__ Wo1, const float* __restrict__ bo1,
    const float* __restrict__ Wo2, const float* __restrict__ bo2,
    const float* __restrict__ Wo3, const float* __restrict__ bo3,
    float* __restrict__ out) {
    __shared__ float yr[HDIM];
    __shared__ float ps[384];
    __shared__ float fs[HDIM];
    const int b   = blockIdx.x;
    const int tid = threadIdx.x;
    const int h   = tid % 96;
    const int g   = tid / 96;   // 0..3

    if (g == 0) {
        float r = b1[h];
#pragma unroll
        for (int pg = 0; pg < 8; pg++)
            r += g_ypart[pg * (BDIM * HDIM) + b * HDIM + h];
        yr[h] = fmaxf(r, 0.f);
    }
    __syncthreads();

    {
        float acc = 0.f;
        const int k0 = g * 24;
#pragma unroll
        for (int k = 0; k < 24; k++)
            acc += yr[k0 + k] * W2[(k0 + k) * HDIM + h];
        ps[tid] = acc;
    }
    __syncthreads();

    if (g == 0) {
        float f = b2[h] + ((ps[h] + ps[h + 96]) + (ps[h + 192] + ps[h + 288]));
        f = fmaxf(f, 0.f);
        fs[h] = f;
        out[b * HDIM + h] = f;
    }
    __syncthreads();

    if (tid < 6) {
        float a = bo1[tid];
        for (int k = 0; k < HDIM; k++) a += fs[k] * Wo1[k * 6 + tid];
        out[6144 + b * 6 + tid] = a;
    } else if (tid == 6) {
        float a = bo2[0];
        for (int k = 0; k < HDIM; k++) a += fs[k] * Wo2[k];
        out[6528 + b] = a;
    } else if (tid < 10) {
        int o = tid - 7;
        float a = bo3[o];
        for (int k = 0; k < HDIM; k++) a += fs[k] * Wo3[k * 3 + o];
        out[6592 + b * 3 + o] = a;
    }
    if (b == 0 && tid == 95) out[6784] = 0.f;  // interloss
}

// ---------------------------------------------------------------------------

extern "C" void kernel_launch(void* const* d_in, const int* in_sizes, int n_in,
                              void* d_out, int out_size) {
    (void)in_sizes; (void)n_in; (void)out_size;
    const float* audios = (const float*)d_in[0];
    const float* texts  = (const float*)d_in[1];
    const float* videos = (const float*)d_in[2];
    const float* Wa  = (const float*)d_in[3];
    const float* ba  = (const float*)d_in[4];
    const float* Wt  = (const float*)d_in[5];
    const float* bt  = (const float*)d_in[6];
    const float* Wv  = (const float*)d_in[7];
    const float* bv  = (const float*)d_in[8];
    const float* W1  = (const float*)d_in[9];
    const float* b1  = (const float*)d_in[10];
    const float* W2  = (const float*)d_in[11];
    const float* b2  = (const float*)d_in[12];
    const float* Wo1 = (const float*)d_in[13];
    const float* bo1 = (const float*)d_in[14];
    const float* Wo2 = (const float*)d_in[15];
    const float* bo2 = (const float*)d_in[16];
    const float* Wo3 = (const float*)d_in[17];
    const float* bo3 = (const float*)d_in[18];
    float* out = (float*)d_out;

    cudaFuncSetAttribute(tfn_main, cudaFuncAttributeMaxDynamicSharedMemorySize,
                         SMEM_BYTES);

    tfn_enc_gemm<<<dim3(64, 16), 192>>>(audios, texts, videos, Wa, Wt, Wv);
    tfn_enc_reduce<<<dim3(64, 3), 96>>>(ba, bt, bv);
    tfn_main<<<2 * NBLK, 256, SMEM_BYTES>>>(W1);
    tfn_tail_a<<<dim3(24, 8), 256>>>();
    tfn_tail_b<<<64, 384>>>(b1, W2, b2, Wo1, bo1, Wo2, bo2, Wo3, bo3, out);
}

// round 17
// speedup vs baseline: 1.0480x; 1.0480x over previous
#include <cuda_runtime.h>
#include <cuda_fp16.h>
#include <cstdint>

// ---------------------------------------------------------------------------
// TFN forward. R17: main kernel FROZEN at its proven floor (per chunk per
// SMSP: 582 LDG.128 @4cyc = 2328 on LSU in parallel with 1164 f32->f16x2
// cvt @rt2 = 2328 on ALU -- both pipes simultaneously at the per-element
// instruction floor; tcgen05/TMA compiler-blocked). This round removes the
// launch tax: 5 kernels -> 3.
//   enc: gemm + last-block fused reduction (atomic ticket, deterministic)
//   main: R16 verbatim
//   tail: merged (38 coalesced loads/thread over L2-warm g_part + W2 + heads)
// ---------------------------------------------------------------------------

#define NBLK   152
#define BDIM   64
#define HDIM   96
#define LDH2   56             // smem B row stride in halfs (112 B)
#define KR2    112            // 97 data rows + 15 zero rows (7 k16 steps)
#define WBUFH2 (KR2 * LDH2)   // 6272 halfs = 12544 B per stage
#define SMEM_BYTES (3*WBUFH2*2 + 6208*4 + 128*4)

__device__ float g_a1[BDIM * 97];
__device__ float g_v1[BDIM * 97];
__device__ float g_t1[BDIM * 97];
__device__ float g_part[NBLK * BDIM * HDIM];
__device__ float g_epart[16 * BDIM * HDIM];   // enc k-slice partials
__device__ int   g_ecnt[3 * BDIM];            // enc last-block tickets (zero-init)

// ---------------------------------------------------------------------------

__device__ __forceinline__ uint32_t h2u(__half2 h) {
    return *reinterpret_cast<uint32_t*>(&h);
}

__device__ __forceinline__ void mma_f16(float c[4],
                                        uint32_t a0, uint32_t a1,
                                        uint32_t a2, uint32_t a3,
                                        uint32_t b0, uint32_t b1) {
    asm volatile(
        "mma.sync.aligned.m16n8k16.row.col.f32.f16.f16.f32 "
        "{%0,%1,%2,%3}, {%4,%5,%6,%7}, {%8,%9}, {%0,%1,%2,%3};"
        : "+f"(c[0]), "+f"(c[1]), "+f"(c[2]), "+f"(c[3])
        : "r"(a0), "r"(a1), "r"(a2), "r"(a3), "r"(b0), "r"(b1));
}

struct __align__(8) H4 { __half2 a, b; };

// CTA loads its N-half of a chunk: 97 rows x 48 cols = 1164 float4.
__device__ __forceinline__ void stage_ldg(float4 (&stg)[5],
                                          const float* __restrict__ W1,
                                          int av, int nh, int tid) {
    const float* src = W1 + (size_t)av * 9312 + nh * 48;
#pragma unroll
    for (int j = 0; j < 4; j++) {
        int q = tid + j * 256;
        int t = q / 12, c = (q - 12 * t) * 4;
        stg[j] = *reinterpret_cast<const float4*>(src + t * 96 + c);
    }
    if (tid < 140) {
        int q = tid + 1024;
        int t = q / 12, c = (q - 12 * t) * 4;
        stg[4] = *reinterpret_cast<const float4*>(src + t * 96 + c);
    }
}

__device__ __forceinline__ void cvt_store(__half* buf, int q, float4 v) {
    int t = q / 12;
    int c = (q - 12 * t) * 4;
    H4 o;
    o.a = __floats2half2_rn(v.x, v.y);
    o.b = __floats2half2_rn(v.z, v.w);
    *reinterpret_cast<H4*>(buf + t * LDH2 + c) = o;
}

__device__ __forceinline__ void stage_sts(__half* buf, const float4 (&stg)[5],
                                          int tid) {
#pragma unroll
    for (int j = 0; j < 4; j++) cvt_store(buf, tid + j * 256, stg[j]);
    if (tid < 140) cvt_store(buf, tid + 1024, stg[4]);
}

// ---------------------------------------------------------------------------
// Kernel 1: enc partial GEMM + fused last-block reduction.
// grid (64 b, 16 modslice), 192 thr = 96h x 2g.
// modslice: 0-3 audio, 4-11 text, 12-15 video; each covers 128 k.
// Last block of a (mod,b) group applies bias+relu+ones and resets its ticket.
// ---------------------------------------------------------------------------
__global__ void __launch_bounds__(192) tfn_enc(
    const float* __restrict__ audios, const float* __restrict__ texts,
    const float* __restrict__ videos,
    const float* __restrict__ Wa, const float* __restrict__ ba,
    const float* __restrict__ Wt, const float* __restrict__ bt,
    const float* __restrict__ Wv, const float* __restrict__ bv) {
    const int b   = blockIdx.x;
    const int ms  = blockIdx.y;
    const int tid = threadIdx.x;

    const float* x; const float* W; int K, k0, mod, nslice, s0;
    if (ms < 4)       { x = audios; W = Wa; K = 512;  k0 = ms * 128;
                        mod = 0; nslice = 4; s0 = 0; }
    else if (ms < 12) { x = texts;  W = Wt; K = 1024; k0 = (ms - 4) * 128;
                        mod = 1; nslice = 8; s0 = 4; }
    else              { x = videos; W = Wv; K = 512;  k0 = (ms - 12) * 128;
                        mod = 2; nslice = 4; s0 = 12; }

    __shared__ float xs[128];
    __shared__ float ps[192];
    __shared__ int   isLast;

    if (tid < 128) xs[tid] = x[(size_t)b * K + k0 + tid];
    __syncthreads();

    const int h = tid % 96;
    const int g = tid / 96;   // 0..1, 64 k each
    const float* Wp = W + (size_t)(k0 + g * 64) * HDIM + h;
    const float* xp = xs + g * 64;

    float acc = 0.f;
#pragma unroll 8
    for (int k = 0; k < 64; k++)
        acc += xp[k] * Wp[k * HDIM];
    ps[tid] = acc;
    __syncthreads();

    if (g == 0)
        g_epart[(ms * 64 + b) * HDIM + h] = ps[h] + ps[h + 96];

    // last-block reduction (CUDA threadFenceReduction pattern)
    __threadfence();
    __syncthreads();
    if (tid == 0) {
        int old = atomicAdd(&g_ecnt[mod * 64 + b], 1);
        isLast = (old == nslice - 1);
        if (isLast) g_ecnt[mod * 64 + b] = 0;   // reset for next graph replay
    }
    __syncthreads();

    if (isLast && tid < 96) {
        const float* bias = (mod == 0) ? ba : (mod == 1) ? bt : bv;
        float* out        = (mod == 0) ? g_a1 : (mod == 1) ? g_t1 : g_v1;
        float r = bias[h];
#pragma unroll
        for (int s = 0; s < 8; s++) {
            if (s < nslice)
                r += g_epart[((s0 + s) * 64 + b) * HDIM + h];
        }
        out[b * 97 + 1 + h] = fmaxf(r, 0.f);
        if (h == 0) out[b * 97] = 1.f;
    }
}

// ---------------------------------------------------------------------------
// Kernel 2: main fused trilinear GEMM (R16 verbatim). grid 304, 256 thr,
// 2 CTAs/SM, prefetch distance 3.
// ---------------------------------------------------------------------------
__global__ void __launch_bounds__(256, 2) tfn_main(const float* __restrict__ W1) {
    extern __shared__ char smx[];
    __half* wb0 = reinterpret_cast<__half*>(smx);
    __half* wb1 = wb0 + WBUFH2;
    __half* wb2 = wb1 + WBUFH2;
    float*  v1s = reinterpret_cast<float*>(wb2 + WBUFH2);  // [64*97]
    float*  a1c = v1s + 6208;                              // [2*64]

    const int tid  = threadIdx.x;
    const int lane = tid & 31;
    const int wid  = tid >> 5;
    const int wm   = wid & 3;
    const int wn   = wid >> 2;
    const int gid  = lane >> 2;
    const int tig  = lane & 3;
    const int b0   = wm * 16 + gid;
    const int nbase = wn * 24;

    const int bk    = blockIdx.x;
    const int range = bk >> 1;
    const int nh    = bk & 1;
    const int cstart = (range < 137) ? range * 62 : range * 61 + 137;
    const int ccnt   = (range < 137) ? 62 : 61;
    const int caBase = cstart / 97;

    for (int i = tid; i < 6208; i += 256) v1s[i] = g_v1[i];
    if (tid < 128) {
        int b = tid & 63, col = tid >> 6;
        int ca = caBase + col; if (ca > 96) ca = 96;
        a1c[col * 64 + b] = g_a1[b * 97 + ca];
    }
    for (int i = tid; i < 3 * 420; i += 256) {
        int s = i / 420, r = i - s * 420;
        reinterpret_cast<uint32_t*>(wb0 + s * WBUFH2 + 97 * LDH2)[r] = 0;
    }

    __half2 t1f[7][4];
#pragma unroll
    for (int ks = 0; ks < 7; ks++) {
        int ka = ks * 16 + 2 * tig;
        int kb = ka + 8;
        float x0 = (ka     < 97) ? g_t1[b0 * 97 + ka]           : 0.f;
        float x1 = (ka + 1 < 97) ? g_t1[b0 * 97 + ka + 1]       : 0.f;
        float y0 = (ka     < 97) ? g_t1[(b0 + 8) * 97 + ka]     : 0.f;
        float y1 = (ka + 1 < 97) ? g_t1[(b0 + 8) * 97 + ka + 1] : 0.f;
        float x2 = (kb     < 97) ? g_t1[b0 * 97 + kb]           : 0.f;
        float x3 = (kb + 1 < 97) ? g_t1[b0 * 97 + kb + 1]       : 0.f;
        float y2 = (kb     < 97) ? g_t1[(b0 + 8) * 97 + kb]     : 0.f;
        float y3 = (kb + 1 < 97) ? g_t1[(b0 + 8) * 97 + kb + 1] : 0.f;
        t1f[ks][0] = __floats2half2_rn(x0, x1);
        t1f[ks][1] = __floats2half2_rn(y0, y1);
        t1f[ks][2] = __floats2half2_rn(x2, x3);
        t1f[ks][3] = __floats2half2_rn(y2, y3);
    }

    float Y[3][4];
#pragma unroll
    for (int j = 0; j < 3; j++) { Y[j][0] = Y[j][1] = Y[j][2] = Y[j][3] = 0.f; }

    const int lrow = lane & 15;
    const int lcol = (lane >> 4) * 8;

    auto compute = [&](int av, const __half* curb) {
        const int ca  = av / 97;
        const int cv  = av - ca * 97;
        const int cai = ca - caBase;
        const __half2 m0h = __float2half2_rn(a1c[cai * 64 + b0] * v1s[b0 * 97 + cv]);
        const __half2 m1h = __float2half2_rn(a1c[cai * 64 + b0 + 8] * v1s[(b0 + 8) * 97 + cv]);
#pragma unroll
        for (int ks = 0; ks < 7; ks++) {
            const uint32_t A0 = h2u(__hmul2(m0h, t1f[ks][0]));
            const uint32_t A1 = h2u(__hmul2(m1h, t1f[ks][1]));
            const uint32_t A2 = h2u(__hmul2(m0h, t1f[ks][2]));
            const uint32_t A3 = h2u(__hmul2(m1h, t1f[ks][3]));
            const __half* rowp = curb + (ks * 16 + lrow) * LDH2 + nbase;

            uint32_t s4 = (uint32_t)__cvta_generic_to_shared(rowp + lcol);
            uint32_t B0, B1, B2, B3;
            asm volatile(
                "ldmatrix.sync.aligned.m8n8.x4.trans.shared.b16 "
                "{%0,%1,%2,%3}, [%4];"
                : "=r"(B0), "=r"(B1), "=r"(B2), "=r"(B3) : "r"(s4));

            uint32_t s2 = (uint32_t)__cvta_generic_to_shared(rowp + 16);
            uint32_t C0, C1;
            asm volatile(
                "ldmatrix.sync.aligned.m8n8.x2.trans.shared.b16 "
                "{%0,%1}, [%2];"
                : "=r"(C0), "=r"(C1) : "r"(s2));

            mma_f16(Y[0], A0, A1, A2, A3, B0, B1);
            mma_f16(Y[1], A0, A1, A2, A3, B2, B3);
            mma_f16(Y[2], A0, A1, A2, A3, C0, C1);
        }
    };

    float4 stgA[5], stgB[5];
    stage_ldg(stgA, W1, cstart, nh, tid);
    if (ccnt > 1) stage_ldg(stgB, W1, cstart + 1, nh, tid);
    stage_sts(wb0, stgA, tid);
    if (ccnt > 2) stage_ldg(stgA, W1, cstart + 2, nh, tid);
    __syncthreads();

    __half *cur = wb0, *nxt = wb1, *spare = wb2;

    for (int ci = 0; ci < ccnt; ci += 2) {
        if (ci + 1 < ccnt) stage_sts(nxt, stgB, tid);
        if (ci + 3 < ccnt) stage_ldg(stgB, W1, cstart + ci + 3, nh, tid);
        compute(cstart + ci, cur);
        __syncthreads();
        { __half* t = cur; cur = nxt; nxt = spare; spare = t; }

        if (ci + 1 < ccnt) {
            if (ci + 2 < ccnt) stage_sts(nxt, stgA, tid);
            if (ci + 4 < ccnt) stage_ldg(stgA, W1, cstart + ci + 4, nh, tid);
            compute(cstart + ci + 1, cur);
            __syncthreads();
            { __half* t = cur; cur = nxt; nxt = spare; spare = t; }
        }
    }

    float* dst = g_part + (size_t)range * (BDIM * HDIM);
#pragma unroll
    for (int j = 0; j < 3; j++) {
        int h = nh * 48 + nbase + 8 * j + 2 * tig;
        *reinterpret_cast<float2*>(dst + b0 * HDIM + h) =
            make_float2(Y[j][0], Y[j][1]);
        *reinterpret_cast<float2*>(dst + (b0 + 8) * HDIM + h) =
            make_float2(Y[j][2], Y[j][3]);
    }
}

// ---------------------------------------------------------------------------
// Kernel 3: merged tail. grid 64, 384 thr = 96h x 4g.
// g_part is L2-warm from main; each thread sums 38 partials (coalesced),
// then bias/relu + W2 (4-way k-split) + heads.
// ---------------------------------------------------------------------------
__global__ void __launch_bounds__(384) tfn_tail(
    const float* __restrict__ b1, const float* __restrict__ W2,
    const float* __restrict__ b2,
    const float* __restrict__ Wo1, const float* __restrict__ bo1,
    const float* __restrict__ Wo2, const float* __restrict__ bo2,
    const float* __restrict__ Wo3, const float* __restrict__ bo3,
    float* __restrict__ out) {
    __shared__ float ps[384];
    __shared__ float yr[HDIM];
    __shared__ float fs[HDIM];
    const int b   = blockIdx.x;
    const int tid = threadIdx.x;
    const int h   = tid % 96;
    const int g   = tid / 96;   // 0..3

    float acc = 0.f;
#pragma unroll
    for (int p = g; p < NBLK; p += 4)
        acc += g_part[(size_t)p * (BDIM * HDIM) + b * HDIM + h];
    ps[tid] = acc;
    __syncthreads();

    if (g == 0) {
        float r = b1[h] + ((ps[h] + ps[h + 96]) + (ps[h + 192] + ps[h + 288]));
        yr[h] = fmaxf(r, 0.f);
    }
    __syncthreads();

    {
        float acc2 = 0.f;
        const int k0 = g * 24;
#pragma unroll
        for (int k = 0; k < 24; k++)
            acc2 += yr[k0 + k] * W2[(k0 + k) * HDIM + h];
        ps[tid] = acc2;
    }
    __syncthreads();

    if (g == 0) {
        float f = b2[h] + ((ps[h] + ps[h + 96]) + (ps[h + 192] + ps[h + 288]));
        f = fmaxf(f, 0.f);
        fs[h] = f;
        out[b * HDIM + h] = f;
    }
    __syncthreads();

    if (tid < 6) {
        float a = bo1[tid];
        for (int k = 0; k < HDIM; k++) a += fs[k] * Wo1[k * 6 + tid];
        out[6144 + b * 6 + tid] = a;
    } else if (tid == 6) {
        float a = bo2[0];
        for (int k = 0; k < HDIM; k++) a += fs[k] * Wo2[k];
        out[6528 + b] = a;
    } else if (tid < 10) {
        int o = tid - 7;
        float a = bo3[o];
        for (int k = 0; k < HDIM; k++) a += fs[k] * Wo3[k * 3 + o];
        out[6592 + b * 3 + o] = a;
    }
    if (b == 0 && tid == 95) out[6784] = 0.f;  // interloss
}

// ---------------------------------------------------------------------------

extern "C" void kernel_launch(void* const* d_in, const int* in_sizes, int n_in,
                              void* d_out, int out_size) {
    (void)in_sizes; (void)n_in; (void)out_size;
    const float* audios = (const float*)d_in[0];
    const float* texts  = (const float*)d_in[1];
    const float* videos = (const float*)d_in[2];
    const float* Wa  = (const float*)d_in[3];
    const float* ba  = (const float*)d_in[4];
    const float* Wt  = (const float*)d_in[5];
    const float* bt  = (const float*)d_in[6];
    const float* Wv  = (const float*)d_in[7];
    const float* bv  = (const float*)d_in[8];
    const float* W1  = (const float*)d_in[9];
    const float* b1  = (const float*)d_in[10];
    const float* W2  = (const float*)d_in[11];
    const float* b2  = (const float*)d_in[12];
    const float* Wo1 = (const float*)d_in[13];
    const float* bo1 = (const float*)d_in[14];
    const float* Wo2 = (const float*)d_in[15];
    const float* bo2 = (const float*)d_in[16];
    const float* Wo3 = (const float*)d_in[17];
    const float* bo3 = (const float*)d_in[18];
    float* out = (float*)d_out;

    cudaFuncSetAttribute(tfn_main, cudaFuncAttributeMaxDynamicSharedMemorySize,
                         SMEM_BYTES);

    tfn_enc<<<dim3(64, 16), 192>>>(audios, texts, videos,
                                   Wa, ba, Wt, bt, Wv, bv);
    tfn_main<<<2 * NBLK, 256, SMEM_BYTES>>>(W1);
    tfn_tail<<<64, 384>>>(b1, W2, b2, Wo1, bo1, Wo2, bo2, Wo3, bo3, out);
}